// round 6
// baseline (speedup 1.0000x reference)
#include <cuda_runtime.h>
#include <cuda_fp16.h>
#include <cstdint>

#define B_SZ  16
#define N_IN  6250
#define N_OUT 25000
#define CCH   64
#define SNB   9
#define NNZ   75000

// fp16 pooled [B][N_OUT][64] = 51.2 MB (written directly by pool_gather)
__device__ unsigned short g_pooled_h[(size_t)B_SZ * N_OUT * CCH];
// transposed split W: [9][n=64][k=64] fp16 hi and lo
__device__ unsigned short g_wt_h[SNB * 64 * 64];
__device__ unsigned short g_wt_l[SNB * 64 * 64];
// CSR scratch for the sparse pool
__device__ int   g_cnt[N_OUT];
__device__ int   g_off[N_OUT + 1];
__device__ int   g_cur[N_OUT];
__device__ int   g_ecol[NNZ];
__device__ float g_eval[NNZ];
// persistent-GEMM work counter
__device__ int   g_work;

// ---------------------------------------------------------------------------
// helpers
// ---------------------------------------------------------------------------
__device__ __forceinline__ uint32_t smem_u32(const void* p) {
    uint32_t a;
    asm("{ .reg .u64 t; cvta.to.shared.u64 t, %1; cvt.u32.u64 %0, t; }"
        : "=r"(a) : "l"(p));
    return a;
}
__device__ __forceinline__ void cp16(uint32_t dst, const void* src) {
    asm volatile("cp.async.cg.shared.global [%0], [%1], 16;"
                 :: "r"(dst), "l"(src) : "memory");
}
__device__ __forceinline__ void cp_commit() {
    asm volatile("cp.async.commit_group;" ::: "memory");
}
template <int N>
__device__ __forceinline__ void cp_wait() {
    asm volatile("cp.async.wait_group %0;" :: "n"(N) : "memory");
}
__device__ __forceinline__ void ldm4(uint32_t* r, uint32_t addr) {
    asm volatile("ldmatrix.sync.aligned.m8n8.x4.shared.b16 {%0,%1,%2,%3}, [%4];"
                 : "=r"(r[0]), "=r"(r[1]), "=r"(r[2]), "=r"(r[3])
                 : "r"(addr));
}
__device__ __forceinline__ void mma16816(float* d, const uint32_t* a,
                                         const uint32_t* b) {
    asm volatile(
        "mma.sync.aligned.m16n8k16.row.col.f32.f16.f16.f32 "
        "{%0,%1,%2,%3},{%4,%5,%6,%7},{%8,%9},{%0,%1,%2,%3};"
        : "+f"(d[0]), "+f"(d[1]), "+f"(d[2]), "+f"(d[3])
        : "r"(a[0]), "r"(a[1]), "r"(a[2]), "r"(a[3]), "r"(b[0]), "r"(b[1]));
}

// ---------------------------------------------------------------------------
// CSR build: zero -> hist -> scan -> scatter
// ---------------------------------------------------------------------------
__global__ void csr_zero() {
    int t = blockIdx.x * blockDim.x + threadIdx.x;
    if (t < N_OUT) g_cnt[t] = 0;
    if (t == 0) g_work = 0;
}

__global__ void csr_hist(const int* __restrict__ tr) {
    int t = blockIdx.x * blockDim.x + threadIdx.x;
    if (t < NNZ) atomicAdd(&g_cnt[__ldg(tr + t)], 1);
}

#define SCAN_T 1024
#define ROWS_PER_T 25
__global__ void __launch_bounds__(SCAN_T) csr_scan() {
    __shared__ int s[SCAN_T];
    const int t = threadIdx.x;
    const int base = t * ROWS_PER_T;
    int local[ROWS_PER_T];
    int sum = 0;
#pragma unroll
    for (int i = 0; i < ROWS_PER_T; i++) {
        int r = base + i;
        local[i] = (r < N_OUT) ? g_cnt[r] : 0;
        sum += local[i];
    }
    s[t] = sum;
    __syncthreads();
    for (int ofs = 1; ofs < SCAN_T; ofs <<= 1) {
        int v = (t >= ofs) ? s[t - ofs] : 0;
        __syncthreads();
        s[t] += v;
        __syncthreads();
    }
    int run = s[t] - sum;
#pragma unroll
    for (int i = 0; i < ROWS_PER_T; i++) {
        int r = base + i;
        if (r < N_OUT) {
            g_off[r] = run;
            g_cur[r] = run;
            run += local[i];
        }
    }
    if (t == SCAN_T - 1) g_off[N_OUT] = NNZ;
}

__global__ void csr_scatter(const float* __restrict__ tv,
                            const int* __restrict__ tr,
                            const int* __restrict__ tc) {
    int t = blockIdx.x * blockDim.x + threadIdx.x;
    if (t >= NNZ) return;
    int row = __ldg(tr + t);
    int pos = atomicAdd(&g_cur[row], 1);
    g_ecol[pos] = __ldg(tc + t);
    g_eval[pos] = __ldg(tv + t);
}

// ---------------------------------------------------------------------------
// pool_gather: one warp per output row, fp32 reg accumulation -> fp16 store
// ---------------------------------------------------------------------------
__global__ void __launch_bounds__(256) pool_gather(const float* __restrict__ x) {
    int t = blockIdx.x * blockDim.x + threadIdx.x;
    if (t >= N_OUT * 32) return;
    const int row = t >> 5;
    const int r   = t & 31;
    const int cg  = r & 15;
    const int b0  = (r >> 4) * 8;

    const int start = g_off[row];
    const int end   = g_off[row + 1];

    float4 acc[8];
#pragma unroll
    for (int b = 0; b < 8; b++) acc[b] = make_float4(0.f, 0.f, 0.f, 0.f);

    const float4* xp = reinterpret_cast<const float4*>(x);
    for (int i = start; i < end; i++) {
        int col = __ldg(g_ecol + i);
        float v = __ldg(g_eval + i);
        const float4* src = xp + ((size_t)b0 * N_IN + col) * 16 + cg;
#pragma unroll
        for (int b = 0; b < 8; b++) {
            float4 xv = src[(size_t)b * N_IN * 16];
            acc[b].x += v * xv.x;
            acc[b].y += v * xv.y;
            acc[b].z += v * xv.z;
            acc[b].w += v * xv.w;
        }
    }
#pragma unroll
    for (int b = 0; b < 8; b++) {
        ushort4 h;
        h.x = __half_as_ushort(__float2half_rn(acc[b].x));
        h.y = __half_as_ushort(__float2half_rn(acc[b].y));
        h.z = __half_as_ushort(__float2half_rn(acc[b].z));
        h.w = __half_as_ushort(__float2half_rn(acc[b].w));
        *reinterpret_cast<ushort4*>(
            g_pooled_h + ((size_t)(b0 + b) * N_OUT + row) * CCH + cg * 4) = h;
    }
}

// ---------------------------------------------------------------------------
// wsplit: transpose + split W -> [9][n=64][k=64] fp16 hi/lo
// ---------------------------------------------------------------------------
__global__ void wsplit_kernel(const float* __restrict__ W) {
    int s = blockIdx.x;
    int n = threadIdx.x;
    unsigned short* dh = g_wt_h + (s * 64 + n) * 64;
    unsigned short* dl = g_wt_l + (s * 64 + n) * 64;
#pragma unroll
    for (int k = 0; k < 64; k++) {
        float w = __ldg(W + (size_t)(s * 64 + k) * 64 + n);
        __half wh = __float2half_rn(w);
        __half wl = __float2half_rn(w - __half2float(wh));
        dh[k] = __half_as_ushort(wh);
        dl[k] = __half_as_ushort(wl);
    }
}

// ---------------------------------------------------------------------------
// persistent fused spiral gather + fp16 2-product GEMM + bias + ELU
// CTA: M=256 x N=64, 512 threads, 16 warps (8x2), warp tile 32x32.
// SMEM: B resident (9 slices x 16KB = 144KB) + A ring 2x32KB = 208KB.
// Work items (tile,b) pulled via atomic counter.
// ---------------------------------------------------------------------------
#define N_TILES   ((N_OUT + 255) / 256)          // 98
#define N_ITEMS   (N_TILES * B_SZ)               // 1568
#define B_TOTAL   (SNB * 16384)                  // 144 KB
#define A_OFF     B_TOTAL
#define A_STG     32768
#define GEMM_SMEM (B_TOTAL + 2 * A_STG)          // 208 KB
#define GRID_P    148

__global__ void __launch_bounds__(512, 1) spiral_gemm_persist(
    const int*   __restrict__ sp,
    const float* __restrict__ bias,
    float*       __restrict__ out) {
    extern __shared__ char smem[];
    const uint32_t sbase = smem_u32(smem);

    const int tid = threadIdx.x;
    const int l   = tid & 31;
    const int wid = tid >> 5;
    const int wm  = wid >> 1;          // 0..7
    const int wn  = wid & 1;           // 0..1
    __shared__ int s_item;

    // ---- prologue: stage ALL W slices (hi+lo) once ----
    for (int i = tid; i < SNB * 1024; i += 512) {
        int s   = i >> 10;
        int r   = i & 1023;
        int row = r >> 3;              // 0..127 (0-63 hi, 64-127 lo)
        int j   = r & 7;
        const unsigned short* src =
            (row < 64 ? g_wt_h + (size_t)(s * 64 + row) * 64
                      : g_wt_l + (size_t)(s * 64 + row - 64) * 64) + j * 8;
        cp16(sbase + s * 16384 + row * 128 + ((j ^ (row & 7)) << 4), src);
    }
    cp_commit();

    // epilogue bias (item-invariant)
    float bias8[4][2];
#pragma unroll
    for (int nj = 0; nj < 4; nj++) {
        int col = wn * 32 + nj * 8 + (l & 3) * 2;
        bias8[nj][0] = __ldg(bias + col);
        bias8[nj][1] = __ldg(bias + col + 1);
    }

    const int arow  = tid >> 1;        // 0..255
    const int ahalf = tid & 1;
    const int rx    = arow & 7;

    while (true) {
        if (tid == 0) s_item = atomicAdd(&g_work, 1);
        __syncthreads();               // publish item; also separates prev
                                       // compute(8) from stageA(0) below
        const int item = s_item;
        if (item >= N_ITEMS) break;
        const int bb = item & 15;
        const int n0 = (item >> 4) * 256;

        const unsigned short* basePH = g_pooled_h + (size_t)bb * N_OUT * CCH;

        int nn = n0 + arow;
        if (nn >= N_OUT) nn = N_OUT - 1;
        int sidx[SNB];
#pragma unroll
        for (int s = 0; s < SNB; s++)
            sidx[s] = __ldg(sp + (size_t)nn * SNB + s);

        auto stageA = [&](int s) {
            const uint32_t stg = sbase + A_OFF + (s & 1) * A_STG;
            const char* src =
                (const char*)(basePH + (size_t)sidx[s] * CCH) + ahalf * 64;
            uint32_t dst = stg + arow * 128;
#pragma unroll
            for (int j = 0; j < 4; j++) {
                int c = ahalf * 4 + j;
                cp16(dst + ((c ^ rx) << 4), src + j * 16);
            }
            cp_commit();
        };

        float acc[2][4][4];
#pragma unroll
        for (int mi = 0; mi < 2; mi++)
#pragma unroll
            for (int nj = 0; nj < 4; nj++)
#pragma unroll
                for (int j = 0; j < 4; j++) acc[mi][nj][j] = 0.f;

        stageA(0);
#pragma unroll
        for (int s = 0; s < SNB; s++) {
            if (s > 0) __syncthreads();   // compute(s-1) done before buffer
                                          // (s+1)&1 == (s-1)&1 is overwritten
            if (s + 1 < SNB) {
                stageA(s + 1);
                cp_wait<1>();
            } else {
                cp_wait<0>();
            }
            __syncthreads();              // staged A(s) visible to all
            const uint32_t stgA = sbase + A_OFF + (s & 1) * A_STG;
            const uint32_t stgB = sbase + s * 16384;
#pragma unroll
            for (int kk = 0; kk < 4; kk++) {
                uint32_t ah[2][4], bh[2][4], bl[2][4];
#pragma unroll
                for (int mi = 0; mi < 2; mi++) {
                    int row = wm * 32 + mi * 16 + (l & 15);
                    int c = kk * 2 + (l >> 4);
                    ldm4(ah[mi], stgA + row * 128 + ((c ^ (row & 7)) << 4));
                }
#pragma unroll
                for (int np = 0; np < 2; np++) {
                    int row = wn * 32 + np * 16 + (l & 7) + ((l >> 4) << 3);
                    int c = kk * 2 + ((l >> 3) & 1);
                    uint32_t addr =
                        stgB + row * 128 + ((c ^ (row & 7)) << 4);
                    ldm4(bh[np], addr);
                    ldm4(bl[np], addr + 8192);
                }
#pragma unroll
                for (int mi = 0; mi < 2; mi++)
#pragma unroll
                    for (int nj = 0; nj < 4; nj++)
                        mma16816(acc[mi][nj], ah[mi],
                                 &bh[nj >> 1][(nj & 1) * 2]);
#pragma unroll
                for (int mi = 0; mi < 2; mi++)
#pragma unroll
                    for (int nj = 0; nj < 4; nj++)
                        mma16816(acc[mi][nj], ah[mi],
                                 &bl[nj >> 1][(nj & 1) * 2]);
            }
        }

        // ---- epilogue: bias + ELU + store ----
#pragma unroll
        for (int mi = 0; mi < 2; mi++) {
#pragma unroll
            for (int half = 0; half < 2; half++) {
                int m = wm * 32 + mi * 16 + (l >> 2) + half * 8;
                int n = n0 + m;
                if (n >= N_OUT) continue;
                float* dst = out + ((size_t)bb * N_OUT + n) * CCH;
#pragma unroll
                for (int nj = 0; nj < 4; nj++) {
                    int col = wn * 32 + nj * 8 + (l & 3) * 2;
                    float t0 = acc[mi][nj][half * 2 + 0] + bias8[nj][0];
                    float t1 = acc[mi][nj][half * 2 + 1] + bias8[nj][1];
                    float2 o;
                    o.x = (t0 > 0.f) ? t0 : expm1f(t0);
                    o.y = (t1 > 0.f) ? t1 : expm1f(t1);
                    *reinterpret_cast<float2*>(dst + col) = o;
                }
            }
        }
    }
}

// ---------------------------------------------------------------------------
extern "C" void kernel_launch(void* const* d_in, const int* in_sizes, int n_in,
                              void* d_out, int out_size) {
    const float* x    = (const float*)d_in[0];
    const float* tv   = (const float*)d_in[1];
    const int*   tr   = (const int*)d_in[2];
    const int*   tc   = (const int*)d_in[3];
    const int*   sp   = (const int*)d_in[4];
    const float* W    = (const float*)d_in[5];
    const float* bias = (const float*)d_in[6];
    float* out = (float*)d_out;

    static bool attr_set = false;
    if (!attr_set) {
        cudaFuncSetAttribute(spiral_gemm_persist,
                             cudaFuncAttributeMaxDynamicSharedMemorySize,
                             GEMM_SMEM);
        attr_set = true;
    }

    csr_zero<<<(N_OUT + 255) / 256, 256>>>();
    csr_hist<<<(NNZ + 255) / 256, 256>>>(tr);
    csr_scan<<<1, SCAN_T>>>();
    csr_scatter<<<(NNZ + 255) / 256, 256>>>(tv, tr, tc);
    wsplit_kernel<<<SNB, 64>>>(W);
    pool_gather<<<(N_OUT * 32 + 255) / 256, 256>>>(x);

    spiral_gemm_persist<<<GRID_P, 512, GEMM_SMEM>>>(sp, bias, out);
}

// round 7
// speedup vs baseline: 1.4363x; 1.4363x over previous
#include <cuda_runtime.h>
#include <cuda_fp16.h>
#include <cstdint>

#define B_SZ  16
#define N_IN  6250
#define N_OUT 25000
#define CCH   64
#define SNB   9
#define NNZ   75000

// fp16 pooled [B][N_OUT][64] = 51.2 MB (written directly by pool_gather)
__device__ unsigned short g_pooled_h[(size_t)B_SZ * N_OUT * CCH];
// transposed W: [9][n=64][k=64] fp16
__device__ unsigned short g_wt_h[SNB * 64 * 64];
// CSR scratch for the sparse pool
__device__ int   g_cnt[N_OUT];
__device__ int   g_off[N_OUT + 1];
__device__ int   g_cur[N_OUT];
__device__ int   g_ecol[NNZ];
__device__ float g_eval[NNZ];

// ---------------------------------------------------------------------------
// helpers
// ---------------------------------------------------------------------------
__device__ __forceinline__ uint32_t smem_u32(const void* p) {
    uint32_t a;
    asm("{ .reg .u64 t; cvta.to.shared.u64 t, %1; cvt.u32.u64 %0, t; }"
        : "=r"(a) : "l"(p));
    return a;
}
__device__ __forceinline__ void cp16(uint32_t dst, const void* src) {
    asm volatile("cp.async.cg.shared.global [%0], [%1], 16;"
                 :: "r"(dst), "l"(src) : "memory");
}
__device__ __forceinline__ void cp_commit() {
    asm volatile("cp.async.commit_group;" ::: "memory");
}
template <int N>
__device__ __forceinline__ void cp_wait() {
    asm volatile("cp.async.wait_group %0;" :: "n"(N) : "memory");
}
__device__ __forceinline__ void ldm4(uint32_t* r, uint32_t addr) {
    asm volatile("ldmatrix.sync.aligned.m8n8.x4.shared.b16 {%0,%1,%2,%3}, [%4];"
                 : "=r"(r[0]), "=r"(r[1]), "=r"(r[2]), "=r"(r[3])
                 : "r"(addr));
}
__device__ __forceinline__ void mma16816(float* d, const uint32_t* a,
                                         const uint32_t* b) {
    asm volatile(
        "mma.sync.aligned.m16n8k16.row.col.f32.f16.f16.f32 "
        "{%0,%1,%2,%3},{%4,%5,%6,%7},{%8,%9},{%0,%1,%2,%3};"
        : "+f"(d[0]), "+f"(d[1]), "+f"(d[2]), "+f"(d[3])
        : "r"(a[0]), "r"(a[1]), "r"(a[2]), "r"(a[3]), "r"(b[0]), "r"(b[1]));
}

// ---------------------------------------------------------------------------
// CSR build: zero -> hist -> scan -> scatter
// ---------------------------------------------------------------------------
__global__ void csr_zero() {
    int t = blockIdx.x * blockDim.x + threadIdx.x;
    if (t < N_OUT) g_cnt[t] = 0;
}

__global__ void csr_hist(const int* __restrict__ tr) {
    int t = blockIdx.x * blockDim.x + threadIdx.x;
    if (t < NNZ) atomicAdd(&g_cnt[__ldg(tr + t)], 1);
}

#define SCAN_T 1024
#define ROWS_PER_T 25
__global__ void __launch_bounds__(SCAN_T) csr_scan() {
    __shared__ int s[SCAN_T];
    const int t = threadIdx.x;
    const int base = t * ROWS_PER_T;
    int local[ROWS_PER_T];
    int sum = 0;
#pragma unroll
    for (int i = 0; i < ROWS_PER_T; i++) {
        int r = base + i;
        local[i] = (r < N_OUT) ? g_cnt[r] : 0;
        sum += local[i];
    }
    s[t] = sum;
    __syncthreads();
    for (int ofs = 1; ofs < SCAN_T; ofs <<= 1) {
        int v = (t >= ofs) ? s[t - ofs] : 0;
        __syncthreads();
        s[t] += v;
        __syncthreads();
    }
    int run = s[t] - sum;
#pragma unroll
    for (int i = 0; i < ROWS_PER_T; i++) {
        int r = base + i;
        if (r < N_OUT) {
            g_off[r] = run;
            g_cur[r] = run;
            run += local[i];
        }
    }
    if (t == SCAN_T - 1) g_off[N_OUT] = NNZ;
}

__global__ void csr_scatter(const float* __restrict__ tv,
                            const int* __restrict__ tr,
                            const int* __restrict__ tc) {
    int t = blockIdx.x * blockDim.x + threadIdx.x;
    if (t >= NNZ) return;
    int row = __ldg(tr + t);
    int pos = atomicAdd(&g_cur[row], 1);
    g_ecol[pos] = __ldg(tc + t);
    g_eval[pos] = __ldg(tv + t);
}

// ---------------------------------------------------------------------------
// pool_gather: one warp per output row, fp32 reg accumulation -> fp16 store
// ---------------------------------------------------------------------------
__global__ void __launch_bounds__(256) pool_gather(const float* __restrict__ x) {
    int t = blockIdx.x * blockDim.x + threadIdx.x;
    if (t >= N_OUT * 32) return;
    const int row = t >> 5;
    const int r   = t & 31;
    const int cg  = r & 15;
    const int b0  = (r >> 4) * 8;

    const int start = g_off[row];
    const int end   = g_off[row + 1];

    float4 acc[8];
#pragma unroll
    for (int b = 0; b < 8; b++) acc[b] = make_float4(0.f, 0.f, 0.f, 0.f);

    const float4* xp = reinterpret_cast<const float4*>(x);
    for (int i = start; i < end; i++) {
        int col = __ldg(g_ecol + i);
        float v = __ldg(g_eval + i);
        const float4* src = xp + ((size_t)b0 * N_IN + col) * 16 + cg;
#pragma unroll
        for (int b = 0; b < 8; b++) {
            float4 xv = src[(size_t)b * N_IN * 16];
            acc[b].x += v * xv.x;
            acc[b].y += v * xv.y;
            acc[b].z += v * xv.z;
            acc[b].w += v * xv.w;
        }
    }
#pragma unroll
    for (int b = 0; b < 8; b++) {
        ushort4 h;
        h.x = __half_as_ushort(__float2half_rn(acc[b].x));
        h.y = __half_as_ushort(__float2half_rn(acc[b].y));
        h.z = __half_as_ushort(__float2half_rn(acc[b].z));
        h.w = __half_as_ushort(__float2half_rn(acc[b].w));
        *reinterpret_cast<ushort4*>(
            g_pooled_h + ((size_t)(b0 + b) * N_OUT + row) * CCH + cg * 4) = h;
    }
}

// ---------------------------------------------------------------------------
// wconv: transpose + convert W -> [9][n=64][k=64] fp16
// ---------------------------------------------------------------------------
__global__ void wconv_kernel(const float* __restrict__ W) {
    int s = blockIdx.x;
    int n = threadIdx.x;
    unsigned short* dh = g_wt_h + (s * 64 + n) * 64;
#pragma unroll
    for (int k = 0; k < 64; k++) {
        float w = __ldg(W + (size_t)(s * 64 + k) * 64 + n);
        dh[k] = __half_as_ushort(__float2half_rn(w));
    }
}

// ---------------------------------------------------------------------------
// fused spiral gather + single-product fp16 GEMM + bias + ELU
// CTA: 128 rows x 64 cols; 256 threads = 8 warps (4x2), warp tile 32x32.
// Stage (24 KB): A 16K | W 8K.  3-stage ring, 1 sync/slice.
// ---------------------------------------------------------------------------
#define B_OFF     16384
#define STAGE_SZ  24576
#define NSTAGE    3
#define GEMM_SMEM (NSTAGE * STAGE_SZ)

__global__ void __launch_bounds__(256, 2) spiral_gemm_mma(
    const int*   __restrict__ sp,
    const float* __restrict__ bias,
    float*       __restrict__ out) {
    extern __shared__ char smem[];
    const uint32_t sbase = smem_u32(smem);

    const int tid = threadIdx.x;
    const int l   = tid & 31;
    const int wid = tid >> 5;
    const int wm  = wid >> 1;
    const int wn  = wid & 1;
    const int b   = blockIdx.y;
    const int n0  = blockIdx.x * 128;

    // staging roles: A = 2 threads per 128B row (128 rows);
    //                B = 4 threads per 128B row (64 rows), 2 cp16 each
    const int arow  = tid >> 1;
    const int ahalf = tid & 1;
    const int brow  = tid >> 2;        // 0..63
    const int bq    = tid & 3;         // quarter (32B)

    const unsigned short* basePH = g_pooled_h + (size_t)b * N_OUT * CCH;

    float acc[2][4][4];
#pragma unroll
    for (int mi = 0; mi < 2; mi++)
#pragma unroll
        for (int nj = 0; nj < 4; nj++)
#pragma unroll
            for (int j = 0; j < 4; j++) acc[mi][nj][j] = 0.f;

    int nn = n0 + arow;
    if (nn >= N_OUT) nn = N_OUT - 1;

    int sidx[SNB];
#pragma unroll
    for (int s = 0; s < SNB; s++) sidx[s] = __ldg(sp + (size_t)nn * SNB + s);

    auto stage = [&](int s) {
        const uint32_t stg = sbase + (s % NSTAGE) * STAGE_SZ;
        // A: gathered row, fp16, 128B per row
        const char* srcA =
            (const char*)(basePH + (size_t)sidx[s] * CCH) + ahalf * 64;
        uint32_t dstA = stg + arow * 128;
        const int rx = arow & 7;
#pragma unroll
        for (int j = 0; j < 4; j++) {
            int c = ahalf * 4 + j;
            cp16(dstA + ((c ^ rx) << 4), srcA + j * 16);
        }
        // B: W slice, 64 rows x 128B, quarter-row per thread
        const char* srcB =
            (const char*)(g_wt_h + (size_t)(s * 64 + brow) * 64) + bq * 32;
        uint32_t dstB = stg + B_OFF + brow * 128;
        const int bx = brow & 7;
#pragma unroll
        for (int j = 0; j < 2; j++) {
            int c = bq * 2 + j;
            cp16(dstB + ((c ^ bx) << 4), srcB + j * 16);
        }
        cp_commit();
    };

    auto compute = [&](int s) {
        const uint32_t stg = sbase + (s % NSTAGE) * STAGE_SZ;
#pragma unroll
        for (int kk = 0; kk < 4; kk++) {
            uint32_t ah[2][4], bh[2][4];
#pragma unroll
            for (int mi = 0; mi < 2; mi++) {
                int row = wm * 32 + mi * 16 + (l & 15);
                int c = kk * 2 + (l >> 4);
                ldm4(ah[mi], stg + row * 128 + ((c ^ (row & 7)) << 4));
            }
#pragma unroll
            for (int np = 0; np < 2; np++) {
                int row = wn * 32 + np * 16 + (l & 7) + ((l >> 4) << 3);
                int c = kk * 2 + ((l >> 3) & 1);
                ldm4(bh[np], stg + B_OFF + row * 128 + ((c ^ (row & 7)) << 4));
            }
#pragma unroll
            for (int mi = 0; mi < 2; mi++)
#pragma unroll
                for (int nj = 0; nj < 4; nj++)
                    mma16816(acc[mi][nj], ah[mi], &bh[nj >> 1][(nj & 1) * 2]);
        }
    };

    stage(0);
    stage(1);
#pragma unroll
    for (int s = 0; s < SNB; s++) {
        cp_wait<1>();
        __syncthreads();
        if (s + 2 < SNB) stage(s + 2);
        else cp_commit();
        compute(s);
    }

    float bias8[4][2];
#pragma unroll
    for (int nj = 0; nj < 4; nj++) {
        int col = wn * 32 + nj * 8 + (l & 3) * 2;
        bias8[nj][0] = __ldg(bias + col);
        bias8[nj][1] = __ldg(bias + col + 1);
    }
#pragma unroll
    for (int mi = 0; mi < 2; mi++) {
#pragma unroll
        for (int half = 0; half < 2; half++) {
            int m = wm * 32 + mi * 16 + (l >> 2) + half * 8;
            int n = n0 + m;
            if (n >= N_OUT) continue;
            float* dst = out + ((size_t)b * N_OUT + n) * CCH;
#pragma unroll
            for (int nj = 0; nj < 4; nj++) {
                int col = wn * 32 + nj * 8 + (l & 3) * 2;
                float t0 = acc[mi][nj][half * 2 + 0] + bias8[nj][0];
                float t1 = acc[mi][nj][half * 2 + 1] + bias8[nj][1];
                float2 o;
                o.x = (t0 > 0.f) ? t0 : expm1f(t0);
                o.y = (t1 > 0.f) ? t1 : expm1f(t1);
                *reinterpret_cast<float2*>(dst + col) = o;
            }
        }
    }
}

// ---------------------------------------------------------------------------
extern "C" void kernel_launch(void* const* d_in, const int* in_sizes, int n_in,
                              void* d_out, int out_size) {
    const float* x    = (const float*)d_in[0];
    const float* tv   = (const float*)d_in[1];
    const int*   tr   = (const int*)d_in[2];
    const int*   tc   = (const int*)d_in[3];
    const int*   sp   = (const int*)d_in[4];
    const float* W    = (const float*)d_in[5];
    const float* bias = (const float*)d_in[6];
    float* out = (float*)d_out;

    static bool attr_set = false;
    if (!attr_set) {
        cudaFuncSetAttribute(spiral_gemm_mma,
                             cudaFuncAttributeMaxDynamicSharedMemorySize,
                             GEMM_SMEM);
        attr_set = true;
    }

    csr_zero<<<(N_OUT + 255) / 256, 256>>>();
    csr_hist<<<(NNZ + 255) / 256, 256>>>(tr);
    csr_scan<<<1, SCAN_T>>>();
    csr_scatter<<<(NNZ + 255) / 256, 256>>>(tv, tr, tc);
    wconv_kernel<<<SNB, 64>>>(W);
    pool_gather<<<(N_OUT * 32 + 255) / 256, 256>>>(x);

    dim3 grid((N_OUT + 127) / 128, B_SZ);
    spiral_gemm_mma<<<grid, 256, GEMM_SMEM>>>(sp, bias, out);
}

// round 8
// speedup vs baseline: 1.5839x; 1.1028x over previous
#include <cuda_runtime.h>
#include <cuda_fp16.h>
#include <cstdint>

#define B_SZ  16
#define N_IN  6250
#define N_OUT 25000
#define CCH   64
#define SNB   9
#define NNZ   75000

// fp16 pooled [B][N_OUT][64] = 51.2 MB
__device__ unsigned short g_pooled_h[(size_t)B_SZ * N_OUT * CCH];
// W in mma-fragment order: [s][kk][nb][lane] -> (b0,b1), 72 KB
__device__ uint2 g_wfrag[SNB * 4 * 8 * 32];
// CSR scratch
__device__ int   g_cnt[N_OUT];
__device__ int   g_off[N_OUT + 1];
__device__ int   g_cur[N_OUT];
__device__ int   g_ecol[NNZ];
__device__ float g_eval[NNZ];

// ---------------------------------------------------------------------------
// helpers
// ---------------------------------------------------------------------------
__device__ __forceinline__ uint32_t smem_u32(const void* p) {
    uint32_t a;
    asm("{ .reg .u64 t; cvta.to.shared.u64 t, %1; cvt.u32.u64 %0, t; }"
        : "=r"(a) : "l"(p));
    return a;
}
__device__ __forceinline__ void cp16(uint32_t dst, const void* src) {
    asm volatile("cp.async.cg.shared.global [%0], [%1], 16;"
                 :: "r"(dst), "l"(src) : "memory");
}
__device__ __forceinline__ void cp_commit() {
    asm volatile("cp.async.commit_group;" ::: "memory");
}
template <int N>
__device__ __forceinline__ void cp_wait() {
    asm volatile("cp.async.wait_group %0;" :: "n"(N) : "memory");
}
__device__ __forceinline__ void ldm4(uint32_t* r, uint32_t addr) {
    asm volatile("ldmatrix.sync.aligned.m8n8.x4.shared.b16 {%0,%1,%2,%3}, [%4];"
                 : "=r"(r[0]), "=r"(r[1]), "=r"(r[2]), "=r"(r[3])
                 : "r"(addr));
}
__device__ __forceinline__ void mma16816(float* d, const uint32_t* a,
                                         const uint32_t* b) {
    asm volatile(
        "mma.sync.aligned.m16n8k16.row.col.f32.f16.f16.f32 "
        "{%0,%1,%2,%3},{%4,%5,%6,%7},{%8,%9},{%0,%1,%2,%3};"
        : "+f"(d[0]), "+f"(d[1]), "+f"(d[2]), "+f"(d[3])
        : "r"(a[0]), "r"(a[1]), "r"(a[2]), "r"(a[3]), "r"(b[0]), "r"(b[1]));
}

// ---------------------------------------------------------------------------
// prep: csr_zero (blocks 0..97) + W fragment build (blocks 98..133)
// ---------------------------------------------------------------------------
#define ZERO_BLOCKS 98
#define WFRAG_BLOCKS 36
__global__ void prep_kernel(const float* __restrict__ W) {
    if (blockIdx.x < ZERO_BLOCKS) {
        int t = blockIdx.x * 256 + threadIdx.x;
        if (t < N_OUT) g_cnt[t] = 0;
        return;
    }
    int i = (blockIdx.x - ZERO_BLOCKS) * 256 + threadIdx.x;  // 0..9215
    if (i >= SNB * 4 * 8 * 32) return;
    int l  = i & 31;
    int nb = (i >> 5) & 7;
    int kk = (i >> 8) & 3;
    int s  = i >> 10;
    int n  = nb * 8 + (l >> 2);
    int k0 = s * 64 + kk * 16 + (l & 3) * 2;
    __half2 b0 = __halves2half2(__float2half_rn(__ldg(W + (size_t)k0 * 64 + n)),
                                __float2half_rn(__ldg(W + (size_t)(k0 + 1) * 64 + n)));
    __half2 b1 = __halves2half2(__float2half_rn(__ldg(W + (size_t)(k0 + 8) * 64 + n)),
                                __float2half_rn(__ldg(W + (size_t)(k0 + 9) * 64 + n)));
    uint2 v;
    v.x = *reinterpret_cast<uint32_t*>(&b0);
    v.y = *reinterpret_cast<uint32_t*>(&b1);
    g_wfrag[i] = v;
}

// ---------------------------------------------------------------------------
// CSR build: hist -> scan -> scatter
// ---------------------------------------------------------------------------
__global__ void csr_hist(const int* __restrict__ tr) {
    int t = blockIdx.x * blockDim.x + threadIdx.x;
    if (t < NNZ) atomicAdd(&g_cnt[__ldg(tr + t)], 1);
}

#define SCAN_T 1024
#define ROWS_PER_T 25
__global__ void __launch_bounds__(SCAN_T) csr_scan() {
    __shared__ int s[SCAN_T];
    const int t = threadIdx.x;
    const int base = t * ROWS_PER_T;
    int local[ROWS_PER_T];
    int sum = 0;
#pragma unroll
    for (int i = 0; i < ROWS_PER_T; i++) {
        int r = base + i;
        local[i] = (r < N_OUT) ? g_cnt[r] : 0;
        sum += local[i];
    }
    s[t] = sum;
    __syncthreads();
    for (int ofs = 1; ofs < SCAN_T; ofs <<= 1) {
        int v = (t >= ofs) ? s[t - ofs] : 0;
        __syncthreads();
        s[t] += v;
        __syncthreads();
    }
    int run = s[t] - sum;
#pragma unroll
    for (int i = 0; i < ROWS_PER_T; i++) {
        int r = base + i;
        if (r < N_OUT) {
            g_off[r] = run;
            g_cur[r] = run;
            run += local[i];
        }
    }
    if (t == SCAN_T - 1) g_off[N_OUT] = NNZ;
}

__global__ void csr_scatter(const float* __restrict__ tv,
                            const int* __restrict__ tr,
                            const int* __restrict__ tc) {
    int t = blockIdx.x * blockDim.x + threadIdx.x;
    if (t >= NNZ) return;
    int row = __ldg(tr + t);
    int pos = atomicAdd(&g_cur[row], 1);
    g_ecol[pos] = __ldg(tc + t);
    g_eval[pos] = __ldg(tv + t);
}

// ---------------------------------------------------------------------------
// pool_gather: one warp per output row, fp32 reg accumulation -> fp16 store
// ---------------------------------------------------------------------------
__global__ void __launch_bounds__(256) pool_gather(const float* __restrict__ x) {
    int t = blockIdx.x * blockDim.x + threadIdx.x;
    if (t >= N_OUT * 32) return;
    const int row = t >> 5;
    const int r   = t & 31;
    const int cg  = r & 15;
    const int b0  = (r >> 4) * 8;

    const int start = g_off[row];
    const int end   = g_off[row + 1];

    float4 acc[8];
#pragma unroll
    for (int b = 0; b < 8; b++) acc[b] = make_float4(0.f, 0.f, 0.f, 0.f);

    const float4* xp = reinterpret_cast<const float4*>(x);
    for (int i = start; i < end; i++) {
        int col = __ldg(g_ecol + i);
        float v = __ldg(g_eval + i);
        const float4* src = xp + ((size_t)b0 * N_IN + col) * 16 + cg;
#pragma unroll
        for (int b = 0; b < 8; b++) {
            float4 xv = src[(size_t)b * N_IN * 16];
            acc[b].x += v * xv.x;
            acc[b].y += v * xv.y;
            acc[b].z += v * xv.z;
            acc[b].w += v * xv.w;
        }
    }
#pragma unroll
    for (int b = 0; b < 8; b++) {
        ushort4 h;
        h.x = __half_as_ushort(__float2half_rn(acc[b].x));
        h.y = __half_as_ushort(__float2half_rn(acc[b].y));
        h.z = __half_as_ushort(__float2half_rn(acc[b].z));
        h.w = __half_as_ushort(__float2half_rn(acc[b].w));
        *reinterpret_cast<ushort4*>(
            g_pooled_h + ((size_t)(b0 + b) * N_OUT + row) * CCH + cg * 4) = h;
    }
}

// ---------------------------------------------------------------------------
// fused spiral gather + fp16 GEMM (B from register fragments) + bias + ELU
// CTA: 128 rows x 64 cols; 256 threads = 8 warps (4x2), warp tile 32x32.
// SMEM: A-only ring, 3 x 16 KB = 48 KB -> 3 CTAs/SM.
// ---------------------------------------------------------------------------
#define STAGE_SZ  16384
#define NSTAGE    3
#define GEMM_SMEM (NSTAGE * STAGE_SZ)

__global__ void __launch_bounds__(256, 3) spiral_gemm_mma(
    const int*   __restrict__ sp,
    const float* __restrict__ bias,
    float*       __restrict__ out) {
    extern __shared__ char smem[];
    const uint32_t sbase = smem_u32(smem);

    const int tid = threadIdx.x;
    const int l   = tid & 31;
    const int wid = tid >> 5;
    const int wm  = wid >> 1;
    const int wn  = wid & 1;
    const int b   = blockIdx.y;
    const int n0  = blockIdx.x * 128;

    const int arow  = tid >> 1;
    const int ahalf = tid & 1;
    const int rx    = arow & 7;

    const unsigned short* basePH = g_pooled_h + (size_t)b * N_OUT * CCH;
    const uint2* wfW = g_wfrag + (wn * 4) * 32 + l;  // warp's n-half, this lane

    float acc[2][4][4];
#pragma unroll
    for (int mi = 0; mi < 2; mi++)
#pragma unroll
        for (int nj = 0; nj < 4; nj++)
#pragma unroll
            for (int j = 0; j < 4; j++) acc[mi][nj][j] = 0.f;

    int nn = n0 + arow;
    if (nn >= N_OUT) nn = N_OUT - 1;

    int sidx[SNB];
#pragma unroll
    for (int s = 0; s < SNB; s++) sidx[s] = __ldg(sp + (size_t)nn * SNB + s);

    auto stage = [&](int s) {
        const uint32_t stg = sbase + (s % NSTAGE) * STAGE_SZ;
        const char* srcA =
            (const char*)(basePH + (size_t)sidx[s] * CCH) + ahalf * 64;
        uint32_t dstA = stg + arow * 128;
#pragma unroll
        for (int j = 0; j < 4; j++) {
            int c = ahalf * 4 + j;
            cp16(dstA + ((c ^ rx) << 4), srcA + j * 16);
        }
        cp_commit();
    };

    auto compute = [&](int s) {
        const uint32_t stg = sbase + (s % NSTAGE) * STAGE_SZ;
#pragma unroll
        for (int kk = 0; kk < 4; kk++) {
            uint32_t ah[2][4];
#pragma unroll
            for (int mi = 0; mi < 2; mi++) {
                int row = wm * 32 + mi * 16 + (l & 15);
                int c = kk * 2 + (l >> 4);
                ldm4(ah[mi], stg + row * 128 + ((c ^ (row & 7)) << 4));
            }
            const uint2* wf = wfW + (size_t)(s * 4 + kk) * 8 * 32;
            uint2 bv[4];
#pragma unroll
            for (int nj = 0; nj < 4; nj++) bv[nj] = __ldg(wf + nj * 32);
#pragma unroll
            for (int mi = 0; mi < 2; mi++)
#pragma unroll
                for (int nj = 0; nj < 4; nj++)
                    mma16816(acc[mi][nj], ah[mi], &bv[nj].x);
        }
    };

    stage(0);
    stage(1);
#pragma unroll
    for (int s = 0; s < SNB; s++) {
        cp_wait<1>();
        __syncthreads();
        if (s + 2 < SNB) stage(s + 2);
        else cp_commit();
        compute(s);
    }

    float bias8[4][2];
#pragma unroll
    for (int nj = 0; nj < 4; nj++) {
        int col = wn * 32 + nj * 8 + (l & 3) * 2;
        bias8[nj][0] = __ldg(bias + col);
        bias8[nj][1] = __ldg(bias + col + 1);
    }
#pragma unroll
    for (int mi = 0; mi < 2; mi++) {
#pragma unroll
        for (int half = 0; half < 2; half++) {
            int m = wm * 32 + mi * 16 + (l >> 2) + half * 8;
            int n = n0 + m;
            if (n >= N_OUT) continue;
            float* dst = out + ((size_t)b * N_OUT + n) * CCH;
#pragma unroll
            for (int nj = 0; nj < 4; nj++) {
                int col = wn * 32 + nj * 8 + (l & 3) * 2;
                float t0 = acc[mi][nj][half * 2 + 0] + bias8[nj][0];
                float t1 = acc[mi][nj][half * 2 + 1] + bias8[nj][1];
                float2 o;
                o.x = (t0 > 0.f) ? t0 : (__expf(t0) - 1.f);
                o.y = (t1 > 0.f) ? t1 : (__expf(t1) - 1.f);
                *reinterpret_cast<float2*>(dst + col) = o;
            }
        }
    }
}

// ---------------------------------------------------------------------------
extern "C" void kernel_launch(void* const* d_in, const int* in_sizes, int n_in,
                              void* d_out, int out_size) {
    const float* x    = (const float*)d_in[0];
    const float* tv   = (const float*)d_in[1];
    const int*   tr   = (const int*)d_in[2];
    const int*   tc   = (const int*)d_in[3];
    const int*   sp   = (const int*)d_in[4];
    const float* W    = (const float*)d_in[5];
    const float* bias = (const float*)d_in[6];
    float* out = (float*)d_out;

    static bool attr_set = false;
    if (!attr_set) {
        cudaFuncSetAttribute(spiral_gemm_mma,
                             cudaFuncAttributeMaxDynamicSharedMemorySize,
                             GEMM_SMEM);
        attr_set = true;
    }

    prep_kernel<<<ZERO_BLOCKS + WFRAG_BLOCKS, 256>>>(W);
    csr_hist<<<(NNZ + 255) / 256, 256>>>(tr);
    csr_scan<<<1, SCAN_T>>>();
    csr_scatter<<<(NNZ + 255) / 256, 256>>>(tv, tr, tc);
    pool_gather<<<(N_OUT * 32 + 255) / 256, 256>>>(x);

    dim3 grid((N_OUT + 127) / 128, B_SZ);
    spiral_gemm_mma<<<grid, 256, GEMM_SMEM>>>(sp, bias, out);
}